// round 13
// baseline (speedup 1.0000x reference)
#include <cuda_runtime.h>
#include <math.h>
#include <stdint.h>

// Problem constants
#define NB 128   // batch
#define TS 512   // timesteps
#define DI 512   // input dim
#define HD 512   // hidden dim

typedef unsigned long long ull;

// ---------------- packed f32x2 helpers (sm_100+ FFMA2 path) ----------------
__device__ __forceinline__ void fma2(ull& acc, ull a, ull b) {
    asm("fma.rn.f32x2 %0, %1, %2, %0;" : "+l"(acc) : "l"(a), "l"(b));
}
__device__ __forceinline__ void add2(ull& a, ull b) {
    asm("add.rn.f32x2 %0, %0, %1;" : "+l"(a) : "l"(b));
}
__device__ __forceinline__ void unpack2(ull v, float& lo, float& hi) {
    unsigned int a, b;
    asm("mov.b64 {%0, %1}, %2;" : "=r"(a), "=r"(b) : "l"(v));
    lo = __uint_as_float(a);
    hi = __uint_as_float(b);
}
__device__ __forceinline__ ull pack_dup(uint32_t h) {
    ull r;
    asm("mov.b64 %0, {%1, %1};" : "=l"(r) : "r"(h));
    return r;
}

#define CLUSTER_ARRIVE() asm volatile("barrier.cluster.arrive.aligned;" ::: "memory")
#define CLUSTER_WAIT()   asm volatile("barrier.cluster.wait.aligned;" ::: "memory")

__device__ __forceinline__ uint32_t smem_u32(const void* p) {
    uint32_t a;
    asm("{ .reg .u64 t; cvta.to.shared.u64 t, %1; cvt.u32.u64 %0, t; }"
        : "=r"(a) : "l"(p));
    return a;
}
__device__ __forceinline__ uint32_t mapa_rank(uint32_t laddr, uint32_t rank) {
    uint32_t r;
    asm("mapa.shared::cluster.u32 %0, %1, %2;" : "=r"(r) : "r"(laddr), "r"(rank));
    return r;
}
__device__ __forceinline__ uint4 ld_cluster_v4(uint32_t addr) {
    uint4 v;
    asm volatile("ld.shared::cluster.v4.b32 {%0,%1,%2,%3}, [%4];"
                 : "=r"(v.x), "=r"(v.y), "=r"(v.z), "=r"(v.w) : "r"(addr));
    return v;
}

// ---------------------------------------------------------------------------
// Kernel 1: xW = x @ Wx + b  (unchanged — proven, rel_err 3.7e-7)
// ---------------------------------------------------------------------------
__global__ __launch_bounds__(256) void xw_gemm(
    const float* __restrict__ A,
    const float* __restrict__ B,
    const float* __restrict__ bias,
    float* __restrict__ C)
{
    __shared__ float2 As2[128][16];
    __shared__ float  Bs[16][128];

    const int m0  = blockIdx.y * 128;
    const int n0  = blockIdx.x * 128;
    const int tid = threadIdx.x;
    const int tn  = tid & 15;
    const int tm  = tid >> 4;

    ull acc[8][4];
#pragma unroll
    for (int i = 0; i < 8; i++)
#pragma unroll
        for (int j = 0; j < 4; j++) acc[i][j] = 0ULL;

    for (int k0 = 0; k0 < DI; k0 += 16) {
#pragma unroll
        for (int j = 0; j < 2; j++) {
            int f  = tid + j * 256;
            int m  = f >> 2;
            int kq = f & 3;
            float4 v = *(const float4*)(A + (size_t)(m0 + m) * DI + k0 + kq * 4);
            *(float4*)(&As2[m][kq * 4])     = make_float4(v.x, v.x, v.y, v.y);
            *(float4*)(&As2[m][kq * 4 + 2]) = make_float4(v.z, v.z, v.w, v.w);
        }
#pragma unroll
        for (int j = 0; j < 2; j++) {
            int f  = tid + j * 256;
            int k  = f >> 5;
            int nq = f & 31;
            *(float4*)(&Bs[k][nq * 4]) =
                *(const float4*)(B + (size_t)(k0 + k) * HD + n0 + nq * 4);
        }
        __syncthreads();

#pragma unroll
        for (int k = 0; k < 16; k++) {
            ulonglong2 b01 = *(const ulonglong2*)(&Bs[k][tn * 8]);
            ulonglong2 b23 = *(const ulonglong2*)(&Bs[k][tn * 8 + 4]);
#pragma unroll
            for (int i = 0; i < 8; i++) {
                ull a = *(const ull*)(&As2[tm * 8 + i][k]);
                fma2(acc[i][0], a, b01.x);
                fma2(acc[i][1], a, b01.y);
                fma2(acc[i][2], a, b23.x);
                fma2(acc[i][3], a, b23.y);
            }
        }
        __syncthreads();
    }

    const float4 bb0 = *(const float4*)(bias + n0 + tn * 8);
    const float4 bb1 = *(const float4*)(bias + n0 + tn * 8 + 4);
#pragma unroll
    for (int i = 0; i < 8; i++) {
        float r0, r1, r2, r3, r4, r5, r6, r7;
        unpack2(acc[i][0], r0, r1);
        unpack2(acc[i][1], r2, r3);
        unpack2(acc[i][2], r4, r5);
        unpack2(acc[i][3], r6, r7);
        float* p = C + (size_t)(m0 + tm * 8 + i) * HD + n0 + tn * 8;
        *(float4*)p       = make_float4(r0 + bb0.x, r1 + bb0.y, r2 + bb0.z, r3 + bb0.w);
        *(float4*)(p + 4) = make_float4(r4 + bb1.x, r5 + bb1.y, r6 + bb1.z, r7 + bb1.w);
    }
}

// ---------------------------------------------------------------------------
// Kernel 2: persistent recurrence — crossbar-floor compute mapping.
//
// Grid: 16 clusters x 8 CTAs. Cluster y: rows [8y,8y+8); CTA x: cols [64x,+64).
//
// SMEM layout (225536 B):
//   Ws  : oct-major Wh slice — oct o in [0,8): region o*16400, row k at k*32,
//         halves at +0/+16. 16400 = 4100 words == 4 mod 32 banks, so the 8
//         octs of a quarter-warp phase cover all 32 banks (conflict-free).
//   Hs  : raw f32 h, row stride 2576, k-swizz off(k) = k*4 + (k>>4)*16 so the
//         4 k-slices inside a warp land on distinct banks.
//   EXP : 2 x 2048 raw h export (double-buffered).
//   RED : [slot][32 ksl] partials, slot stride 272 B. Store pattern banks =
//         16(grp&1)+4j+2ksl — all 32 lanes distinct; load 4-phase floor.
//
// Per step: thread (ksl=tid>>3, grp=tid&7) computes 8 rows x 4 colpairs over
// k in [16 ksl, 16 ksl+16): per k = 8 LDS.32 + 8 pack + 2 LDS.128 + 32 FFMA2
// (2 B per FFMA2 — crossbar == FFMA2 pipe floor, 2048 cyc/SM/step).
// Reduce 32 partials/slot in smem; thread tid finalizes slot tid (xw + tanh +
// STG + export). One barrier.cluster, then warp pw pulls rank pw's raw 2KB
// via mapa + ld.shared::cluster into swizzled Hs. Pull skipped on last step.
// ---------------------------------------------------------------------------
#define HR      2576                        // Hs row stride (644 words ≡ 4 banks)
#define WS_OFF  0
#define WOCT    16400                       // Ws oct region stride
#define HS_OFF  131200                      // 8*16400
#define EXP_OFF (HS_OFF + 8 * HR)           // 151808
#define RED_OFF (EXP_OFF + 2 * 2048)        // 155904
#define SMEM_RNN_BYTES (RED_OFF + 256 * 272) // 225536

__global__ __launch_bounds__(256, 1) __cluster_dims__(8, 1, 1)
void rnn_persistent(const float* __restrict__ Wh,
                    const float* __restrict__ h0,
                    float* __restrict__ out)
{
    extern __shared__ char smem[];
    const uint32_t sbase = smem_u32(smem);

    const int tid = threadIdx.x;
    const int m0  = blockIdx.y * 8;
    const int n0  = blockIdx.x * 64;

    // ---- load Wh slice once into oct-major layout: 8192 float4, 32/thread ----
#pragma unroll 4
    for (int j = 0; j < 32; j++) {
        int f   = tid + j * 256;
        int k   = f >> 4;
        int nq  = f & 15;             // float4 index within 64 cols
        int oct = nq >> 1;
        int hf  = nq & 1;
        *(float4*)(smem + WS_OFF + (size_t)oct * WOCT + k * 32 + hf * 16) =
            *(const float4*)(Wh + (size_t)k * HD + n0 + nq * 4);
    }

    // ---- stage h0 raw+swizzled: 1024 float4, 4/thread ----
#pragma unroll
    for (int j = 0; j < 4; j++) {
        int f   = tid + j * 256;
        int row = f >> 7;
        int q   = f & 127;            // float4 index (k = 4q)
        *(float4*)(smem + HS_OFF + row * HR + q * 16 + (q >> 2) * 16) =
            *(const float4*)(h0 + (size_t)(m0 + row) * HD + q * 4);
    }
    __syncthreads();

    // compute decomposition: 32 k-slices x 8 col-octs
    const int ksl = tid >> 3;          // 0..31, k in [16ksl, 16ksl+16)
    const int grp = tid & 7;           // col oct: colpairs grp*4..grp*4+3

    const char* hb = smem + HS_OFF + ksl * 80;                 // + r*HR + kk*4
    const char* wb = smem + WS_OFF + (size_t)grp * WOCT + ksl * 512; // + kk*32

    // partial-store base: slot = r*32 + grp*4 + j  ->  RED + slot*272 + ksl*8
    char* pstore = smem + RED_OFF + (grp * 4) * 272 + ksl * 8;

    // epilogue slot: row = tid>>5, colpair = tid&31
    const int er  = tid >> 5;
    const int ecp = tid & 31;

    // pull mapping: warp pw pulls rank pw's 2KB raw export
    const int pw    = tid >> 5;
    const int lane  = tid & 31;
    const int prow  = lane >> 2;
    const int ppart = lane & 3;
    // Hs offset for k-range [pw*64+ppart*16, +16): pw*320 + ppart*80
    char* pd = smem + HS_OFF + prow * HR + pw * 320 + ppart * 80;

    for (int t = 0; t < TS; t++) {
        // xw prefetch for this thread's slot (hidden behind compute loop)
        float* pio = out + ((size_t)(m0 + er) * TS + t) * HD + n0 + ecp * 2;
        float2 xw = *(const float2*)pio;

        // ---- 8x8 register-blocked partial GEMM over 16 k ----
        ull acc[8][4];
#pragma unroll
        for (int r = 0; r < 8; r++)
#pragma unroll
            for (int j = 0; j < 4; j++) acc[r][j] = 0ULL;

#pragma unroll 8
        for (int kk = 0; kk < 16; kk++) {
            ull hp[8];
#pragma unroll
            for (int r = 0; r < 8; r++)
                hp[r] = pack_dup(*(const uint32_t*)(hb + r * HR + kk * 4));
            ulonglong2 wA = *(const ulonglong2*)(wb + kk * 32);
            ulonglong2 wB = *(const ulonglong2*)(wb + kk * 32 + 16);
#pragma unroll
            for (int r = 0; r < 8; r++) {
                fma2(acc[r][0], hp[r], wA.x);
                fma2(acc[r][1], hp[r], wA.y);
                fma2(acc[r][2], hp[r], wB.x);
                fma2(acc[r][3], hp[r], wB.y);
            }
        }

        // ---- dump 32 partials (bank-clean: 16(grp&1)+4j+2ksl all distinct) ----
#pragma unroll
        for (int r = 0; r < 8; r++)
#pragma unroll
            for (int j = 0; j < 4; j++)
                *(ull*)(pstore + (size_t)r * 32 * 272 + j * 272) = acc[r][j];
        __syncthreads();

        // ---- final reduce (32 partials) + epilogue: thread tid = slot tid ----
        {
            const char* rb = smem + RED_OFF + tid * 272;
            ulonglong2 v[16];
#pragma unroll
            for (int q = 0; q < 16; q++)
                v[q] = *(const ulonglong2*)(rb + q * 16);
            // pairwise tree over 32 ull values
            ull s[8];
#pragma unroll
            for (int q = 0; q < 8; q++) {
                ull a = v[2 * q].x;
                add2(a, v[2 * q].y);
                ull b = v[2 * q + 1].x;
                add2(b, v[2 * q + 1].y);
                add2(a, b);
                s[q] = a;
            }
            add2(s[0], s[1]); add2(s[2], s[3]); add2(s[4], s[5]); add2(s[6], s[7]);
            add2(s[0], s[2]); add2(s[4], s[6]);
            add2(s[0], s[4]);

            float slo, shi;
            unpack2(s[0], slo, shi);
            float2 hv;
            hv.x = tanhf(xw.x + slo);
            hv.y = tanhf(xw.y + shi);

            // output (never re-read: no fence needed)
            *(float2*)pio = hv;

            // raw export (double-buffered, 2KB = 8 rows x 256B)
            *(float2*)(smem + EXP_OFF + (t & 1) * 2048 + er * 256 + ecp * 8) = hv;
        }

        // ---- cluster-wide exchange barrier (release/acquire) ----
        CLUSTER_ARRIVE();
        CLUSTER_WAIT();

        // ---- pull all 8 ranks' raw exports into swizzled Hs ----
        // Skipped on final step: no peer-SMEM access after the last barrier.
        if (t < TS - 1) {
            uint32_t src = mapa_rank(
                sbase + EXP_OFF + (t & 1) * 2048 + prow * 256 + ppart * 64, pw);
#pragma unroll
            for (int i = 0; i < 4; i++) {
                uint4 v = ld_cluster_v4(src + i * 16);
                *(uint4*)(pd + i * 16) = v;
            }
        }
        __syncthreads();
    }
}

// ---------------------------------------------------------------------------
// Launch
// ---------------------------------------------------------------------------
extern "C" void kernel_launch(void* const* d_in, const int* in_sizes, int n_in,
                              void* d_out, int out_size) {
    (void)in_sizes; (void)n_in; (void)out_size;
    const float* x  = (const float*)d_in[0];   // [128, 512, 512]
    const float* h0 = (const float*)d_in[1];   // [128, 512]
    const float* Wx = (const float*)d_in[2];   // [512, 512]
    const float* Wh = (const float*)d_in[3];   // [512, 512]
    const float* b  = (const float*)d_in[4];   // [512]
    float* out = (float*)d_out;                // [128, 512, 512]

    dim3 gx(HD / 128, (NB * TS) / 128);        // (4, 512)
    xw_gemm<<<gx, 256>>>(x, Wx, b, out);

    cudaFuncSetAttribute(rnn_persistent,
                         cudaFuncAttributeMaxDynamicSharedMemorySize,
                         SMEM_RNN_BYTES);
    dim3 gs(8, NB / 8);                        // 8 CTAs/cluster x 16 clusters
    rnn_persistent<<<gs, 256, SMEM_RNN_BYTES>>>(Wh, h0, out);
}